// round 4
// baseline (speedup 1.0000x reference)
#include <cuda_runtime.h>
#include <cuda_bf16.h>
#include <cstdint>
#include <math.h>

// Problem constants (fixed by the reference)
#define HDIM 1024
#define IEDIM 256
#define NEXP 8
#define VOCAB 100000

// Scratch for transposed weights (no cudaMalloc allowed).
// MUST be 16B aligned: we read them via int4 (LDG.128 traps on misalign).
__device__ __align__(16) int8_t g_gate_t[NEXP * IEDIM * HDIM];  // [E][IE][H]  2 MB
__device__ __align__(16) int8_t g_up_t  [NEXP * IEDIM * HDIM];  // [E][IE][H]  2 MB
__device__ __align__(16) int8_t g_down_t[NEXP * HDIM * IEDIM];  // [E][H][IE]  2 MB

// Weight storage-representation flag, written by detect_kernel each launch:
// 0 = packed int8, 1 = int32 (sign-extended int8), 2 = float32, 3 = bfloat16
__device__ int g_wtype;

__global__ void detect_kernel(const void* __restrict__ w) {
    // Single block, 1 warp. Vote over first 256 elements under each hypothesis.
    if (threadIdx.x != 0) return;
    const int N = 256;
    int v_i32 = 0, v_f32 = 0, v_bf16 = 0;
    const int*   wi = (const int*)w;
    const float* wf = (const float*)w;
    const __nv_bfloat16* wb = (const __nv_bfloat16*)w;
    for (int i = 0; i < N; i++) {
        int iv = wi[i];
        if (iv >= -128 && iv <= 127) v_i32++;
        float fv = wf[i];
        if (fv == rintf(fv) && fabsf(fv) <= 127.0f) v_f32++;
        float bv = __bfloat162float(wb[i]);
        if (bv == rintf(bv) && fabsf(bv) <= 127.0f) v_bf16++;
    }
    int wt = 0;
    if      (v_i32  >= (N * 9) / 10) wt = 1;
    else if (v_f32  >= (N * 9) / 10) wt = 2;
    else if (v_bf16 >= (N * 9) / 10) wt = 3;
    g_wtype = wt;
}

__device__ __forceinline__ int8_t load_w(const void* __restrict__ src, size_t idx, int wt) {
    switch (wt) {
        case 1:  return (int8_t)((const int*)src)[idx];
        case 2:  return (int8_t)(int)rintf(((const float*)src)[idx]);
        case 3:  return (int8_t)(int)rintf(__bfloat162float(((const __nv_bfloat16*)src)[idx]));
        default: return ((const int8_t*)src)[idx];
    }
}

// Per-expert 2D transpose with on-the-fly dtype decode:
// src logical [E][R][C] (any storage repr) -> dst [E][C][R] packed int8
__global__ void transpose_kernel(const void* __restrict__ src,
                                 int8_t* __restrict__ dst,
                                 int R, int C) {
    __shared__ int8_t tile[32][33];
    int wt = g_wtype;
    int e = blockIdx.z;
    int cbase = blockIdx.x * 32;
    int rbase = blockIdx.y * 32;
    int tx = threadIdx.x;           // 0..31
    int ty = threadIdx.y;           // 0..7
    size_t base = (size_t)e * R * C;
    int8_t* d = dst + (size_t)e * C * R;
#pragma unroll
    for (int j = 0; j < 4; j++) {
        int r = rbase + ty + 8 * j;
        tile[ty + 8 * j][tx] = load_w(src, base + (size_t)r * C + cbase + tx, wt);
    }
    __syncthreads();
#pragma unroll
    for (int j = 0; j < 4; j++) {
        int c = cbase + ty + 8 * j;
        d[(size_t)c * R + rbase + tx] = tile[tx][ty + 8 * j];
    }
}

__device__ __forceinline__ float block_absmax(float v, float* red) {
#pragma unroll
    for (int off = 16; off > 0; off >>= 1)
        v = fmaxf(v, __shfl_xor_sync(0xffffffffu, v, off));
    int wid = threadIdx.x >> 5;
    int lane = threadIdx.x & 31;
    if (lane == 0) red[wid] = v;
    __syncthreads();
    float m = red[0];
#pragma unroll
    for (int w = 1; w < 8; w++) m = fmaxf(m, red[w]);
    __syncthreads();
    return m;
}

__device__ __forceinline__ int clamp_q(float r) {
    int a = (int)rintf(r);           // round-half-even, matches jnp.round
    a = max(-128, min(127, a));
    return a;
}

__global__ __launch_bounds__(256, 4)
void moe_token_kernel(const float* __restrict__ x,
                      const int* __restrict__ token_ids,
                      const float* __restrict__ gate_scale,   // [E][IE]
                      const float* __restrict__ up_scale,     // [E][IE]
                      const float* __restrict__ down_scale,   // [E][H]
                      const int* __restrict__ t2e,            // [V]
                      float* __restrict__ out) {
    int token = blockIdx.x;
    int t = threadIdx.x;

    __shared__ __align__(16) int   xq[HDIM / 4];       // 256 packed words
    __shared__ float red[8];
    __shared__ int   s_e;
    __shared__ __align__(16) signed char iqb[IEDIM];   // quantized intermediate

    if (t == 0) {
        int id = token_ids[token];
        id = min(max(id, 0), VOCAB - 1);
        s_e = t2e[id];
    }

    // ---- load x row (4 floats/thread), rowwise quantize ----
    const float4 xv = reinterpret_cast<const float4*>(x + (size_t)token * HDIM)[t];
    float m = fmaxf(fmaxf(fabsf(xv.x), fabsf(xv.y)), fmaxf(fabsf(xv.z), fabsf(xv.w)));
    m = block_absmax(m, red);
    float xscale = fmaxf(m / 127.0f, 1e-8f);

    int a0 = clamp_q(xv.x / xscale);
    int a1 = clamp_q(xv.y / xscale);
    int a2 = clamp_q(xv.z / xscale);
    int a3 = clamp_q(xv.w / xscale);
    xq[t] = (a0 & 0xff) | ((a1 & 0xff) << 8) | ((a2 & 0xff) << 16) | (a3 << 24);
    __syncthreads();

    int e = s_e;

    // ---- gate/up GEMV: thread t computes intermediate column t ----
    const int4* gw = reinterpret_cast<const int4*>(g_gate_t + ((size_t)(e * IEDIM + t)) * HDIM);
    const int4* uw = reinterpret_cast<const int4*>(g_up_t   + ((size_t)(e * IEDIM + t)) * HDIM);
    const int4* xw4 = reinterpret_cast<const int4*>(xq);
    int ga = 0, ua = 0;
#pragma unroll 4
    for (int k = 0; k < HDIM / 16; k++) {        // 64 iterations
        int4 xk = xw4[k];
        int4 g  = gw[k];
        int4 u  = uw[k];
        ga = __dp4a(xk.x, g.x, ga); ga = __dp4a(xk.y, g.y, ga);
        ga = __dp4a(xk.z, g.z, ga); ga = __dp4a(xk.w, g.w, ga);
        ua = __dp4a(xk.x, u.x, ua); ua = __dp4a(xk.y, u.y, ua);
        ua = __dp4a(xk.z, u.z, ua); ua = __dp4a(xk.w, u.w, ua);
    }
    float gf = (float)ga * xscale * gate_scale[e * IEDIM + t];
    float uf = (float)ua * xscale * up_scale[e * IEDIM + t];
    float sig = 1.0f / (1.0f + expf(-gf));
    float inter = gf * sig * uf;

    // ---- rowwise quantize intermediate ----
    float mi = block_absmax(fabsf(inter), red);
    float iscale = fmaxf(mi / 127.0f, 1e-8f);
    iqb[t] = (signed char)clamp_q(inter / iscale);
    __syncthreads();

    // ---- down GEMV: thread t computes outputs h = t + 256*j ----
    const int4* iq4 = reinterpret_cast<const int4*>(iqb);
    float* orow = out + (size_t)token * HDIM;
#pragma unroll
    for (int j = 0; j < 4; j++) {
        int h = t + 256 * j;
        const int4* dw = reinterpret_cast<const int4*>(g_down_t + ((size_t)(e * HDIM + h)) * IEDIM);
        int acc = 0;
#pragma unroll 4
        for (int k = 0; k < IEDIM / 16; k++) {    // 16 iterations
            int4 ik = iq4[k];
            int4 d  = dw[k];
            acc = __dp4a(ik.x, d.x, acc); acc = __dp4a(ik.y, d.y, acc);
            acc = __dp4a(ik.z, d.z, acc); acc = __dp4a(ik.w, d.w, acc);
        }
        orow[h] = (float)acc * iscale * down_scale[e * HDIM + h];
    }
}

extern "C" void kernel_launch(void* const* d_in, const int* in_sizes, int n_in,
                              void* d_out, int out_size) {
    const float* hidden      = (const float*)d_in[0];
    const int*   token_ids   = (const int*)d_in[1];
    const void*  gate_q      = d_in[2];                 // int8 logical; repr auto-detected
    const float* gate_scale  = (const float*)d_in[3];
    const void*  up_q        = d_in[4];
    const float* up_scale    = (const float*)d_in[5];
    const void*  down_q      = d_in[6];
    const float* down_scale  = (const float*)d_in[7];
    const int*   t2e         = (const int*)d_in[8];
    float* out = (float*)d_out;

    int T = in_sizes[0] / HDIM;   // 16384 tokens

    int8_t *gate_t_ptr, *up_t_ptr, *down_t_ptr;
    cudaGetSymbolAddress((void**)&gate_t_ptr, g_gate_t);
    cudaGetSymbolAddress((void**)&up_t_ptr,   g_up_t);
    cudaGetSymbolAddress((void**)&down_t_ptr, g_down_t);

    // Detect the storage representation of the (logically int8) weights.
    detect_kernel<<<1, 32>>>(gate_q);

    // Transpose (+decode) weights into dot-product-friendly int8 layouts.
    // gate/up: [E][H][IE] -> [E][IE][H]   (R=H, C=IE)
    {
        dim3 grid(IEDIM / 32, HDIM / 32, NEXP), blk(32, 8);
        transpose_kernel<<<grid, blk>>>(gate_q, gate_t_ptr, HDIM, IEDIM);
        transpose_kernel<<<grid, blk>>>(up_q,   up_t_ptr,   HDIM, IEDIM);
    }
    // down: [E][IE][H] -> [E][H][IE]      (R=IE, C=H)
    {
        dim3 grid(HDIM / 32, IEDIM / 32, NEXP), blk(32, 8);
        transpose_kernel<<<grid, blk>>>(down_q, down_t_ptr, IEDIM, HDIM);
    }

    moe_token_kernel<<<T, 256>>>(hidden, token_ids, gate_scale, up_scale,
                                 down_scale, t2e, out);
}

// round 6
// speedup vs baseline: 9.7265x; 9.7265x over previous
#include <cuda_runtime.h>
#include <cuda_bf16.h>
#include <cstdint>
#include <math.h>

#define HDIM 1024
#define IEDIM 256
#define NEXP 8
#define VOCAB 100000
#define TMAX 16384
#define TILE_M 128

// ---------------- device scratch (no cudaMalloc allowed) ----------------
__device__ __align__(16) int8_t g_xq[TMAX * HDIM];            // 16 MB quantized x
__device__ float  g_xs[TMAX];
__device__ __align__(16) int8_t g_iq[TMAX * IEDIM];           // 4 MB quantized intermediate
__device__ float  g_is[TMAX];
__device__ __align__(16) float  g_inter[TMAX * IEDIM];        // 16 MB fp32 intermediate
__device__ __align__(16) int8_t g_w1[NEXP * 2 * IEDIM * HDIM];// 4 MB packed [e][512][1024]
__device__ __align__(16) int8_t g_down_t[NEXP * HDIM * IEDIM];// 2 MB [e][H][IE]
__device__ int g_eid[TMAX];
__device__ int g_perm[TMAX];
__device__ int g_counts[NEXP];
__device__ int g_cursor[NEXP];
__device__ int g_off[NEXP + 1];
__device__ int g_wtype;   // 0=int8 1=int32 2=f32 3=bf16

// ---------------- dtype probe ----------------
__global__ void detect_kernel(const void* __restrict__ w) {
    if (threadIdx.x != 0) return;
    const int N = 256;
    int v_i32 = 0, v_f32 = 0, v_bf16 = 0;
    const int* wi = (const int*)w;
    const float* wf = (const float*)w;
    const __nv_bfloat16* wb = (const __nv_bfloat16*)w;
    for (int i = 0; i < N; i++) {
        int iv = wi[i];
        if (iv >= -128 && iv <= 127) v_i32++;
        float fv = wf[i];
        if (fv == rintf(fv) && fabsf(fv) <= 127.0f) v_f32++;
        float bv = __bfloat162float(wb[i]);
        if (bv == rintf(bv) && fabsf(bv) <= 127.0f) v_bf16++;
    }
    int wt = 0;
    if      (v_i32  >= (N * 9) / 10) wt = 1;
    else if (v_f32  >= (N * 9) / 10) wt = 2;
    else if (v_bf16 >= (N * 9) / 10) wt = 3;
    g_wtype = wt;
}

__device__ __forceinline__ int8_t load_w(const void* __restrict__ src, size_t idx, int wt) {
    switch (wt) {
        case 1:  return (int8_t)((const int*)src)[idx];
        case 2:  return (int8_t)(int)rintf(((const float*)src)[idx]);
        case 3:  return (int8_t)(int)rintf(__bfloat162float(((const __nv_bfloat16*)src)[idx]));
        default: return ((const int8_t*)src)[idx];
    }
}

__global__ void reset_kernel() {
    int t = threadIdx.x;
    if (t < NEXP) { g_counts[t] = 0; g_cursor[t] = 0; }
}

// ---------------- weight prep ----------------
// Pack W1[e][n(512)][k(1024)]: n block p=n>>6, i=n&63: i<32 -> gate col p*32+i, else up col p*32+i-32
__global__ void pack_w1_kernel(const void* __restrict__ gate_q, const void* __restrict__ up_q) {
    __shared__ int8_t tile[32][33];
    int wt = g_wtype;
    int e = blockIdx.z;
    int kbase = blockIdx.x * 32;   // over H
    int nbase = blockIdx.y * 32;   // over 512 combined
    int tx = threadIdx.x, ty = threadIdx.y;
    int p = nbase >> 6;
    int isup = (nbase >> 5) & 1;
    int colbase = p * 32;
    const void* src = isup ? up_q : gate_q;
#pragma unroll
    for (int j = 0; j < 4; j++) {
        int h = kbase + ty + 8 * j;
        tile[ty + 8 * j][tx] = load_w(src, ((size_t)e * HDIM + h) * IEDIM + colbase + tx, wt);
    }
    __syncthreads();
#pragma unroll
    for (int j = 0; j < 4; j++) {
        int n = nbase + ty + 8 * j;
        g_w1[((size_t)e * 512 + n) * HDIM + kbase + tx] = tile[tx][ty + 8 * j];
    }
}

// down: [E][IE][H] -> [E][H][IE]
__global__ void transpose_down_kernel(const void* __restrict__ src) {
    __shared__ int8_t tile[32][33];
    int wt = g_wtype;
    int e = blockIdx.z;
    int cbase = blockIdx.x * 32;   // over H (C)
    int rbase = blockIdx.y * 32;   // over IE (R)
    int tx = threadIdx.x, ty = threadIdx.y;
    size_t base = (size_t)e * IEDIM * HDIM;
#pragma unroll
    for (int j = 0; j < 4; j++) {
        int r = rbase + ty + 8 * j;
        tile[ty + 8 * j][tx] = load_w(src, base + (size_t)r * HDIM + cbase + tx, wt);
    }
    __syncthreads();
#pragma unroll
    for (int j = 0; j < 4; j++) {
        int c = cbase + ty + 8 * j;
        g_down_t[((size_t)e * HDIM + c) * IEDIM + rbase + tx] = tile[tx][ty + 8 * j];
    }
}

// ---------------- quantize x + expert id (1 warp / token) ----------------
__device__ __forceinline__ int clamp_q(float r) {
    int a = (int)rintf(r);
    return max(-128, min(127, a));
}

__global__ void quant_x_kernel(const float* __restrict__ x,
                               const int* __restrict__ token_ids,
                               const int* __restrict__ t2e, int T) {
    int w = threadIdx.x >> 5, lane = threadIdx.x & 31;
    int token = blockIdx.x * 8 + w;
    if (token >= T) return;
    const float4* row = (const float4*)(x + (size_t)token * HDIM);
    float4 v[8];
    float m = 0.f;
#pragma unroll
    for (int j = 0; j < 8; j++) {
        v[j] = row[lane * 8 + j];
        m = fmaxf(m, fmaxf(fmaxf(fabsf(v[j].x), fabsf(v[j].y)), fmaxf(fabsf(v[j].z), fabsf(v[j].w))));
    }
#pragma unroll
    for (int off = 16; off > 0; off >>= 1)
        m = fmaxf(m, __shfl_xor_sync(0xffffffffu, m, off));
    float scale = fmaxf(m / 127.0f, 1e-8f);
    int* dst = (int*)(g_xq + (size_t)token * HDIM);
#pragma unroll
    for (int j = 0; j < 8; j++) {
        int a0 = clamp_q(v[j].x / scale), a1 = clamp_q(v[j].y / scale);
        int a2 = clamp_q(v[j].z / scale), a3 = clamp_q(v[j].w / scale);
        dst[lane * 8 + j] = (a0 & 0xff) | ((a1 & 0xff) << 8) | ((a2 & 0xff) << 16) | (a3 << 24);
    }
    if (lane == 0) {
        g_xs[token] = scale;
        int id = token_ids[token];
        id = min(max(id, 0), VOCAB - 1);
        int e = t2e[id];
        g_eid[token] = e;
        atomicAdd(&g_counts[e], 1);
    }
}

__global__ void scan_kernel() {
    if (threadIdx.x == 0) {
        g_off[0] = 0;
        for (int e = 0; e < NEXP; e++) g_off[e + 1] = g_off[e] + g_counts[e];
    }
}

__global__ void scatter_kernel(int T) {
    int t = blockIdx.x * blockDim.x + threadIdx.x;
    if (t >= T) return;
    int e = g_eid[t];
    int pos = atomicAdd(&g_cursor[e], 1);
    g_perm[g_off[e] + pos] = t;
}

// ---------------- rowwise quantize intermediate (1 warp / token) ----------------
__global__ void quant_i_kernel(int T) {
    int w = threadIdx.x >> 5, lane = threadIdx.x & 31;
    int token = blockIdx.x * 8 + w;
    if (token >= T) return;
    const float4* row = (const float4*)(g_inter + (size_t)token * IEDIM);
    float4 v[2];
    float m = 0.f;
#pragma unroll
    for (int j = 0; j < 2; j++) {
        v[j] = row[lane * 2 + j];
        m = fmaxf(m, fmaxf(fmaxf(fabsf(v[j].x), fabsf(v[j].y)), fmaxf(fabsf(v[j].z), fabsf(v[j].w))));
    }
#pragma unroll
    for (int off = 16; off > 0; off >>= 1)
        m = fmaxf(m, __shfl_xor_sync(0xffffffffu, m, off));
    float scale = fmaxf(m / 127.0f, 1e-8f);
    int* dst = (int*)(g_iq + (size_t)token * IEDIM);
#pragma unroll
    for (int j = 0; j < 2; j++) {
        int a0 = clamp_q(v[j].x / scale), a1 = clamp_q(v[j].y / scale);
        int a2 = clamp_q(v[j].z / scale), a3 = clamp_q(v[j].w / scale);
        dst[lane * 2 + j] = (a0 & 0xff) | ((a1 & 0xff) << 8) | ((a2 & 0xff) << 16) | (a3 << 24);
    }
    if (lane == 0) g_is[token] = scale;
}

// ---------------- mma helpers ----------------
__device__ __forceinline__ void mma_s8(int* c, const unsigned* a, const unsigned* b) {
    asm volatile(
        "mma.sync.aligned.m16n8k32.row.col.s32.s8.s8.s32 "
        "{%0,%1,%2,%3},{%4,%5,%6,%7},{%8,%9},{%0,%1,%2,%3};"
        : "+r"(c[0]), "+r"(c[1]), "+r"(c[2]), "+r"(c[3])
        : "r"(a[0]), "r"(a[1]), "r"(a[2]), "r"(a[3]), "r"(b[0]), "r"(b[1]));
}

// smem tile: [rows][128B], 16B-chunk xor swizzle by (row&7)
__device__ __forceinline__ unsigned lds32(const char* base, int row, int k) {
    return *(const unsigned*)(base + row * 128 + ((((k >> 4) & 7) ^ (row & 7)) << 4) + (k & 15));
}

// map flat tile id -> (expert, tile, cnt, off); returns false if out of range
__device__ __forceinline__ bool map_tile(int bx, int& e, int& tile, int& cnt, int& off) {
    int acc = 0;
    for (int i = 0; i < NEXP; i++) {
        int c = g_off[i + 1] - g_off[i];
        int nt = (c + TILE_M - 1) >> 7;
        if (bx < acc + nt) { e = i; tile = bx - acc; cnt = c; off = g_off[i]; return true; }
        acc += nt;
    }
    return false;
}

// ---------------- GEMM1: xq(128) @ W1(64 cols = 32 gate + 32 up) -> inter ----------------
__global__ __launch_bounds__(256, 2)
void gemm1_kernel(const float* __restrict__ gate_scale,
                  const float* __restrict__ up_scale) {
    __shared__ __align__(16) char smem[24576];
    char* sA = smem;                 // 128*128
    char* sB = smem + 16384;         // 64*128
    float* epi = (float*)smem;       // reused: [128][36]

    int e, tile, cnt, off;
    if (!map_tile(blockIdx.x, e, tile, cnt, off)) return;
    int p = blockIdx.y;              // channel block 0..7 (32 channels)

    int t = threadIdx.x;
    int wid = t >> 5, lane = t & 31;
    int wm = wid & 3, wn = wid >> 2;
    int g = lane >> 2, tig = lane & 3;

    int c[2][4][4];
#pragma unroll
    for (int a = 0; a < 2; a++)
#pragma unroll
        for (int b = 0; b < 4; b++)
#pragma unroll
            for (int i = 0; i < 4; i++) c[a][b][i] = 0;

    int arow = t >> 1;
    int am = tile * TILE_M + arow;
    int atok = g_perm[off + min(am, cnt - 1)];
    const int4* asrc_base = (const int4*)(g_xq + (size_t)atok * HDIM);
    int achunk0 = (t & 1) * 4;
    int brow = t >> 2;               // 0..63 combined col within tile
    int gcol = p * 64 + brow;
    const int4* bsrc_base = (const int4*)(g_w1 + ((size_t)e * 512 + gcol) * HDIM);
    int bchunk0 = (t & 3) * 2;

    for (int kc = 0; kc < HDIM / 128; kc++) {
        const int4* asrc = asrc_base + kc * 8;
#pragma unroll
        for (int ii = 0; ii < 4; ii++) {
            int ch = achunk0 + ii;
            ((int4*)(sA + arow * 128))[ch ^ (arow & 7)] = asrc[ch];
        }
        const int4* bsrc = bsrc_base + kc * 8;
#pragma unroll
        for (int ii = 0; ii < 2; ii++) {
            int ch = bchunk0 + ii;
            ((int4*)(sB + brow * 128))[ch ^ (brow & 7)] = bsrc[ch];
        }
        __syncthreads();

#pragma unroll
        for (int ks = 0; ks < 4; ks++) {
            int kb = ks * 32 + tig * 4;
            unsigned a[2][4], b[4][2];
#pragma unroll
            for (int mt = 0; mt < 2; mt++) {
                int r0 = wm * 32 + mt * 16 + g;
                a[mt][0] = lds32(sA, r0,     kb);
                a[mt][1] = lds32(sA, r0 + 8, kb);
                a[mt][2] = lds32(sA, r0,     kb + 16);
                a[mt][3] = lds32(sA, r0 + 8, kb + 16);
            }
#pragma unroll
            for (int nt = 0; nt < 4; nt++) {
                int col = wn * 32 + nt * 8 + g;
                b[nt][0] = lds32(sB, col, kb);
                b[nt][1] = lds32(sB, col, kb + 16);
            }
#pragma unroll
            for (int mt = 0; mt < 2; mt++)
#pragma unroll
                for (int nt = 0; nt < 4; nt++)
                    mma_s8(c[mt][nt], a[mt], b[nt]);
        }
        __syncthreads();
    }

    // ---- epilogue: wn0 = gate, wn1 = up (same channel index); combine via smem ----
    float xsv[2][2];
#pragma unroll
    for (int mt = 0; mt < 2; mt++) {
#pragma unroll
        for (int hh = 0; hh < 2; hh++) {
            int row = wm * 32 + mt * 16 + g + hh * 8;
            int m = tile * TILE_M + row;
            int tok = g_perm[off + min(m, cnt - 1)];
            xsv[mt][hh] = g_xs[tok];
        }
    }

    if (wn == 0) {
#pragma unroll
        for (int mt = 0; mt < 2; mt++)
#pragma unroll
            for (int nt = 0; nt < 4; nt++)
#pragma unroll
                for (int i = 0; i < 4; i++) {
                    int hh = i >> 1;
                    int row = wm * 32 + mt * 16 + g + hh * 8;
                    int cL = nt * 8 + tig * 2 + (i & 1);
                    float gs = gate_scale[e * IEDIM + p * 32 + cL];
                    epi[row * 36 + cL] = (float)c[mt][nt][i] * xsv[mt][hh] * gs;
                }
    }
    __syncthreads();
    if (wn == 1) {
#pragma unroll
        for (int mt = 0; mt < 2; mt++)
#pragma unroll
            for (int nt = 0; nt < 4; nt++)
#pragma unroll
                for (int i = 0; i < 4; i++) {
                    int hh = i >> 1;
                    int row = wm * 32 + mt * 16 + g + hh * 8;
                    int cL = nt * 8 + tig * 2 + (i & 1);
                    float us = up_scale[e * IEDIM + p * 32 + cL];
                    float u = (float)c[mt][nt][i] * xsv[mt][hh] * us;
                    float gv = epi[row * 36 + cL];
                    float sig = 1.0f / (1.0f + expf(-gv));
                    epi[row * 36 + cL] = gv * sig * u;
                }
    }
    __syncthreads();
#pragma unroll
    for (int q = 0; q < 4; q++) {
        int f4 = t + q * 256;
        int row = f4 >> 3, c4 = f4 & 7;
        int m = tile * TILE_M + row;
        if (m < cnt) {
            int tok = g_perm[off + m];
            *(float4*)(g_inter + (size_t)tok * IEDIM + p * 32 + c4 * 4) =
                *(float4*)(epi + row * 36 + c4 * 4);
        }
    }
}

// ---------------- GEMM2: iq(128) @ down(64 cols) -> out ----------------
__global__ __launch_bounds__(256, 2)
void gemm2_kernel(const float* __restrict__ down_scale, float* __restrict__ out) {
    __shared__ __align__(16) char smem[24576];
    char* sA = smem;
    char* sB = smem + 16384;

    int e, tile, cnt, off;
    if (!map_tile(blockIdx.x, e, tile, cnt, off)) return;
    int nb = blockIdx.y;             // 0..15, 64 cols each

    int t = threadIdx.x;
    int wid = t >> 5, lane = t & 31;
    int wm = wid & 3, wn = wid >> 2;
    int g = lane >> 2, tig = lane & 3;

    int c[2][4][4];
#pragma unroll
    for (int a = 0; a < 2; a++)
#pragma unroll
        for (int b = 0; b < 4; b++)
#pragma unroll
            for (int i = 0; i < 4; i++) c[a][b][i] = 0;

    int arow = t >> 1;
    int am = tile * TILE_M + arow;
    int atok = g_perm[off + min(am, cnt - 1)];
    const int4* asrc_base = (const int4*)(g_iq + (size_t)atok * IEDIM);
    int achunk0 = (t & 1) * 4;
    int brow = t >> 2;
    int gcol = nb * 64 + brow;       // 0..1023
    const int4* bsrc_base = (const int4*)(g_down_t + ((size_t)e * HDIM + gcol) * IEDIM);
    int bchunk0 = (t & 3) * 2;

    for (int kc = 0; kc < IEDIM / 128; kc++) {   // 2 chunks
        const int4* asrc = asrc_base + kc * 8;
#pragma unroll
        for (int ii = 0; ii < 4; ii++) {
            int ch = achunk0 + ii;
            ((int4*)(sA + arow * 128))[ch ^ (arow & 7)] = asrc[ch];
        }
        const int4* bsrc = bsrc_base + kc * 8;
#pragma unroll
        for (int ii = 0; ii < 2; ii++) {
            int ch = bchunk0 + ii;
            ((int4*)(sB + brow * 128))[ch ^ (brow & 7)] = bsrc[ch];
        }
        __syncthreads();

#pragma unroll
        for (int ks = 0; ks < 4; ks++) {
            int kb = ks * 32 + tig * 4;
            unsigned a[2][4], b[4][2];
#pragma unroll
            for (int mt = 0; mt < 2; mt++) {
                int r0 = wm * 32 + mt * 16 + g;
                a[mt][0] = lds32(sA, r0,     kb);
                a[mt][1] = lds32(sA, r0 + 8, kb);
                a[mt][2] = lds32(sA, r0,     kb + 16);
                a[mt][3] = lds32(sA, r0 + 8, kb + 16);
            }
#pragma unroll
            for (int nt = 0; nt < 4; nt++) {
                int col = wn * 32 + nt * 8 + g;
                b[nt][0] = lds32(sB, col, kb);
                b[nt][1] = lds32(sB, col, kb + 16);
            }
#pragma unroll
            for (int mt = 0; mt < 2; mt++)
#pragma unroll
                for (int nt = 0; nt < 4; nt++)
                    mma_s8(c[mt][nt], a[mt], b[nt]);
        }
        __syncthreads();
    }

    // epilogue: direct scaled stores.  FIX: column index must include wn*32.
#pragma unroll
    for (int mt = 0; mt < 2; mt++) {
#pragma unroll
        for (int hh = 0; hh < 2; hh++) {
            int row = wm * 32 + mt * 16 + g + hh * 8;
            int m = tile * TILE_M + row;
            if (m >= cnt) continue;
            int tok = g_perm[off + m];
            float isv = g_is[tok];
            float* orow = out + (size_t)tok * HDIM + nb * 64;
#pragma unroll
            for (int nt = 0; nt < 4; nt++) {
#pragma unroll
                for (int ii = 0; ii < 2; ii++) {
                    int i = hh * 2 + ii;
                    int cL = wn * 32 + nt * 8 + tig * 2 + ii;
                    float ds = down_scale[e * HDIM + nb * 64 + cL];
                    orow[cL] = (float)c[mt][nt][i] * isv * ds;
                }
            }
        }
    }
}

// ---------------- launch ----------------
extern "C" void kernel_launch(void* const* d_in, const int* in_sizes, int n_in,
                              void* d_out, int out_size) {
    const float* hidden      = (const float*)d_in[0];
    const int*   token_ids   = (const int*)d_in[1];
    const void*  gate_q      = d_in[2];
    const float* gate_scale  = (const float*)d_in[3];
    const void*  up_q        = d_in[4];
    const float* up_scale    = (const float*)d_in[5];
    const void*  down_q      = d_in[6];
    const float* down_scale  = (const float*)d_in[7];
    const int*   t2e         = (const int*)d_in[8];
    float* out = (float*)d_out;

    int T = in_sizes[0] / HDIM;     // 16384

    detect_kernel<<<1, 32>>>(gate_q);
    reset_kernel<<<1, 32>>>();

    {
        dim3 grid(HDIM / 32, 512 / 32, NEXP), blk(32, 8);
        pack_w1_kernel<<<grid, blk>>>(gate_q, up_q);
    }
    {
        dim3 grid(HDIM / 32, IEDIM / 32, NEXP), blk(32, 8);
        transpose_down_kernel<<<grid, blk>>>(down_q);
    }

    quant_x_kernel<<<(T + 7) / 8, 256>>>(hidden, token_ids, t2e, T);
    scan_kernel<<<1, 32>>>();
    scatter_kernel<<<(T + 255) / 256, 256>>>(T);

    int ntiles = (T + TILE_M - 1) / TILE_M + NEXP;
    {
        dim3 grid(ntiles, 8);
        gemm1_kernel<<<grid, 256>>>(gate_scale, up_scale);
    }
    quant_i_kernel<<<(T + 7) / 8, 256>>>(T);
    {
        dim3 grid(ntiles, 16);
        gemm2_kernel<<<grid, 256>>>(down_scale, out);
    }
}

// round 7
// speedup vs baseline: 11.3403x; 1.1659x over previous
#include <cuda_runtime.h>
#include <cuda_bf16.h>
#include <cstdint>
#include <math.h>

#define HDIM 1024
#define IEDIM 256
#define NEXP 8
#define VOCAB 100000
#define TMAX 16384
#define TILE_M 128

// ---------------- device scratch (no cudaMalloc allowed) ----------------
__device__ __align__(16) int8_t g_xq[TMAX * HDIM];
__device__ float  g_xs[TMAX];
__device__ __align__(16) int8_t g_iq[TMAX * IEDIM];
__device__ float  g_is[TMAX];
__device__ __align__(16) float  g_inter[TMAX * IEDIM];
__device__ __align__(16) int8_t g_w1[NEXP * 2 * IEDIM * HDIM]; // [e][512][1024]
__device__ __align__(16) int8_t g_down_t[NEXP * HDIM * IEDIM]; // [e][H][IE]
__device__ int g_eid[TMAX];
__device__ int g_perm[TMAX];
__device__ int g_counts[NEXP];
__device__ int g_cursor[NEXP];
__device__ int g_off[NEXP + 1];
__device__ int g_wtype;   // 0=int8 1=int32 2=f32 3=bf16

// ---------------- async-copy / ldmatrix helpers ----------------
__device__ __forceinline__ uint32_t smem_u32(const void* p) {
    return (uint32_t)__cvta_generic_to_shared(p);
}
__device__ __forceinline__ void cp16(void* s, const void* g) {
    asm volatile("cp.async.cg.shared.global [%0], [%1], 16;\n"
                 :: "r"(smem_u32(s)), "l"(g));
}
__device__ __forceinline__ void cp_commit() {
    asm volatile("cp.async.commit_group;\n");
}
template <int N>
__device__ __forceinline__ void cp_wait() {
    asm volatile("cp.async.wait_group %0;\n" :: "n"(N));
}
__device__ __forceinline__ void ldsm_x4(uint32_t* r, uint32_t addr) {
    asm volatile("ldmatrix.sync.aligned.m8n8.x4.shared.b16 {%0,%1,%2,%3}, [%4];"
                 : "=r"(r[0]), "=r"(r[1]), "=r"(r[2]), "=r"(r[3]) : "r"(addr));
}
__device__ __forceinline__ void mma_s8(int* c, const unsigned* a, const unsigned* b) {
    asm volatile(
        "mma.sync.aligned.m16n8k32.row.col.s32.s8.s8.s32 "
        "{%0,%1,%2,%3},{%4,%5,%6,%7},{%8,%9},{%0,%1,%2,%3};"
        : "+r"(c[0]), "+r"(c[1]), "+r"(c[2]), "+r"(c[3])
        : "r"(a[0]), "r"(a[1]), "r"(a[2]), "r"(a[3]), "r"(b[0]), "r"(b[1]));
}

// ---------------- dtype probe + counter reset (merged, parallel) ----------------
__global__ void detect_reset_kernel(const void* __restrict__ w) {
    int t = threadIdx.x;   // 256 threads
    if (t < NEXP) { g_counts[t] = 0; g_cursor[t] = 0; }
    int iv = ((const int*)w)[t];
    bool ok_i32 = (iv >= -128 && iv <= 127);
    float fv = ((const float*)w)[t];
    bool ok_f32 = (fv == rintf(fv) && fabsf(fv) <= 127.0f);
    float bv = __bfloat162float(((const __nv_bfloat16*)w)[t]);
    bool ok_bf16 = (bv == rintf(bv) && fabsf(bv) <= 127.0f);
    int c1 = __syncthreads_count(ok_i32);
    int c2 = __syncthreads_count(ok_f32);
    int c3 = __syncthreads_count(ok_bf16);
    if (t == 0) {
        int wt = 0;
        if      (c1 >= 230) wt = 1;
        else if (c2 >= 230) wt = 2;
        else if (c3 >= 230) wt = 3;
        g_wtype = wt;
    }
}

__device__ __forceinline__ int8_t load_w(const void* __restrict__ src, size_t idx, int wt) {
    switch (wt) {
        case 1:  return (int8_t)((const int*)src)[idx];
        case 2:  return (int8_t)(int)rintf(((const float*)src)[idx]);
        case 3:  return (int8_t)(int)rintf(__bfloat162float(((const __nv_bfloat16*)src)[idx]));
        default: return ((const int8_t*)src)[idx];
    }
}

// ---------------- weight prep ----------------
__global__ void pack_w1_kernel(const void* __restrict__ gate_q, const void* __restrict__ up_q) {
    __shared__ int8_t tile[32][33];
    int wt = g_wtype;
    int e = blockIdx.z;
    int kbase = blockIdx.x * 32;   // over H
    int nbase = blockIdx.y * 32;   // over 512 combined
    int tx = threadIdx.x, ty = threadIdx.y;
    int p = nbase >> 6;
    int isup = (nbase >> 5) & 1;
    int colbase = p * 32;
    const void* src = isup ? up_q : gate_q;
#pragma unroll
    for (int j = 0; j < 4; j++) {
        int h = kbase + ty + 8 * j;
        tile[ty + 8 * j][tx] = load_w(src, ((size_t)e * HDIM + h) * IEDIM + colbase + tx, wt);
    }
    __syncthreads();
#pragma unroll
    for (int j = 0; j < 4; j++) {
        int n = nbase + ty + 8 * j;
        g_w1[((size_t)e * 512 + n) * HDIM + kbase + tx] = tile[tx][ty + 8 * j];
    }
}

__global__ void transpose_down_kernel(const void* __restrict__ src) {
    __shared__ int8_t tile[32][33];
    int wt = g_wtype;
    int e = blockIdx.z;
    int cbase = blockIdx.x * 32;   // over H
    int rbase = blockIdx.y * 32;   // over IE
    int tx = threadIdx.x, ty = threadIdx.y;
    size_t base = (size_t)e * IEDIM * HDIM;
#pragma unroll
    for (int j = 0; j < 4; j++) {
        int r = rbase + ty + 8 * j;
        tile[ty + 8 * j][tx] = load_w(src, base + (size_t)r * HDIM + cbase + tx, wt);
    }
    __syncthreads();
#pragma unroll
    for (int j = 0; j < 4; j++) {
        int c = cbase + ty + 8 * j;
        g_down_t[((size_t)e * HDIM + c) * IEDIM + rbase + tx] = tile[tx][ty + 8 * j];
    }
}

// ---------------- quantize x + expert id (1 warp / token, coalesced) ----------------
__device__ __forceinline__ int clamp_q(float r) {
    int a = (int)rintf(r);
    return max(-128, min(127, a));
}

__global__ void quant_x_kernel(const float* __restrict__ x,
                               const int* __restrict__ token_ids,
                               const int* __restrict__ t2e, int T) {
    int w = threadIdx.x >> 5, lane = threadIdx.x & 31;
    int token = blockIdx.x * 8 + w;
    if (token >= T) return;
    const float4* row = (const float4*)(x + (size_t)token * HDIM);
    float4 v[8];
    float m = 0.f;
#pragma unroll
    for (int j = 0; j < 8; j++) {
        v[j] = row[j * 32 + lane];                 // coalesced
        m = fmaxf(m, fmaxf(fmaxf(fabsf(v[j].x), fabsf(v[j].y)), fmaxf(fabsf(v[j].z), fabsf(v[j].w))));
    }
#pragma unroll
    for (int off = 16; off > 0; off >>= 1)
        m = fmaxf(m, __shfl_xor_sync(0xffffffffu, m, off));
    float scale = fmaxf(m / 127.0f, 1e-8f);
    int* dst = (int*)(g_xq + (size_t)token * HDIM);
#pragma unroll
    for (int j = 0; j < 8; j++) {
        int a0 = clamp_q(v[j].x / scale), a1 = clamp_q(v[j].y / scale);
        int a2 = clamp_q(v[j].z / scale), a3 = clamp_q(v[j].w / scale);
        dst[j * 32 + lane] = (a0 & 0xff) | ((a1 & 0xff) << 8) | ((a2 & 0xff) << 16) | (a3 << 24);
    }
    if (lane == 0) {
        g_xs[token] = scale;
        int id = token_ids[token];
        id = min(max(id, 0), VOCAB - 1);
        int e = t2e[id];
        g_eid[token] = e;
        atomicAdd(&g_counts[e], 1);
    }
}

__global__ void scan_kernel() {
    if (threadIdx.x == 0) {
        g_off[0] = 0;
        for (int e = 0; e < NEXP; e++) g_off[e + 1] = g_off[e] + g_counts[e];
    }
}

__global__ void scatter_kernel(int T) {
    int t = blockIdx.x * blockDim.x + threadIdx.x;
    if (t >= T) return;
    int e = g_eid[t];
    int pos = atomicAdd(&g_cursor[e], 1);
    g_perm[g_off[e] + pos] = t;
}

// ---------------- rowwise quantize intermediate (coalesced) ----------------
__global__ void quant_i_kernel(int T) {
    int w = threadIdx.x >> 5, lane = threadIdx.x & 31;
    int token = blockIdx.x * 8 + w;
    if (token >= T) return;
    const float4* row = (const float4*)(g_inter + (size_t)token * IEDIM);
    float4 v[2];
    float m = 0.f;
#pragma unroll
    for (int j = 0; j < 2; j++) {
        v[j] = row[j * 32 + lane];
        m = fmaxf(m, fmaxf(fmaxf(fabsf(v[j].x), fabsf(v[j].y)), fmaxf(fabsf(v[j].z), fabsf(v[j].w))));
    }
#pragma unroll
    for (int off = 16; off > 0; off >>= 1)
        m = fmaxf(m, __shfl_xor_sync(0xffffffffu, m, off));
    float scale = fmaxf(m / 127.0f, 1e-8f);
    int* dst = (int*)(g_iq + (size_t)token * IEDIM);
#pragma unroll
    for (int j = 0; j < 2; j++) {
        int a0 = clamp_q(v[j].x / scale), a1 = clamp_q(v[j].y / scale);
        int a2 = clamp_q(v[j].z / scale), a3 = clamp_q(v[j].w / scale);
        dst[j * 32 + lane] = (a0 & 0xff) | ((a1 & 0xff) << 8) | ((a2 & 0xff) << 16) | (a3 << 24);
    }
    if (lane == 0) g_is[token] = scale;
}

// map flat tile id -> (expert, tile, cnt, off)
__device__ __forceinline__ bool map_tile(int bx, int& e, int& tile, int& cnt, int& off) {
    int acc = 0;
    for (int i = 0; i < NEXP; i++) {
        int c = g_off[i + 1] - g_off[i];
        int nt = (c + TILE_M - 1) >> 7;
        if (bx < acc + nt) { e = i; tile = bx - acc; cnt = c; off = g_off[i]; return true; }
        acc += nt;
    }
    return false;
}

// fragment loads via ldmatrix over xor-swizzled [row][128B] tiles
__device__ __forceinline__ uint32_t tile_addr(uint32_t base_u32, int row, int k16) {
    // k16: byte offset, multiple of 16
    return base_u32 + row * 128 + (((((k16) >> 4) & 7) ^ (row & 7)) << 4);
}

// ---------------- GEMM1: xq(128) @ W1(64 cols) -> inter, pipelined ----------------
__global__ __launch_bounds__(256, 2)
void gemm1_kernel(const float* __restrict__ gate_scale,
                  const float* __restrict__ up_scale) {
    __shared__ __align__(16) char smem[49152];
    char* sA = smem;                 // 2 stages x 16384
    char* sB = smem + 32768;         // 2 stages x 8192
    float* epi = (float*)smem;       // reused: [128][36]

    int e, tile, cnt, off;
    if (!map_tile(blockIdx.x, e, tile, cnt, off)) return;
    int p = blockIdx.y;              // 0..7

    int t = threadIdx.x;
    int wid = t >> 5, lane = t & 31;
    int wm = wid & 3, wn = wid >> 2;
    int g = lane >> 2, tig = lane & 3;

    int c[2][4][4];
#pragma unroll
    for (int a = 0; a < 2; a++)
#pragma unroll
        for (int b = 0; b < 4; b++)
#pragma unroll
            for (int i = 0; i < 4; i++) c[a][b][i] = 0;

    int arow = t >> 1;
    int am = tile * TILE_M + arow;
    int atok = g_perm[off + min(am, cnt - 1)];
    const int4* asrc_base = (const int4*)(g_xq + (size_t)atok * HDIM);
    int achunk0 = (t & 1) * 4;
    int brow = t >> 2;
    int gcol = p * 64 + brow;
    const int4* bsrc_base = (const int4*)(g_w1 + ((size_t)e * 512 + gcol) * HDIM);
    int bchunk0 = (t & 3) * 2;

    uint32_t sA_u32 = smem_u32(sA);
    uint32_t sB_u32 = smem_u32(sB);

    // ldmatrix per-lane address components
    int a_row_off = (lane & 7) + ((lane & 8) ? 8 : 0);
    int a_k_off   = (lane & 16) ? 16 : 0;
    int b_row_off = (lane & 7) + ((lane & 16) ? 8 : 0);
    int b_k_off   = (lane & 8) ? 16 : 0;

    auto load_stage = [&](int kc, int stg) {
        int4* da = (int4*)(sA + stg * 16384 + arow * 128);
        const int4* asrc = asrc_base + kc * 8;
#pragma unroll
        for (int ii = 0; ii < 4; ii++) {
            int ch = achunk0 + ii;
            cp16(&da[ch ^ (arow & 7)], &asrc[ch]);
        }
        int4* db = (int4*)(sB + stg * 8192 + brow * 128);
        const int4* bsrc = bsrc_base + kc * 8;
#pragma unroll
        for (int ii = 0; ii < 2; ii++) {
            int ch = bchunk0 + ii;
            cp16(&db[ch ^ (brow & 7)], &bsrc[ch]);
        }
    };

    load_stage(0, 0);
    cp_commit();

#pragma unroll 1
    for (int kc = 0; kc < HDIM / 128; kc++) {
        if (kc + 1 < HDIM / 128) {
            load_stage(kc + 1, (kc + 1) & 1);
            cp_commit();
            cp_wait<1>();
        } else {
            cp_wait<0>();
        }
        __syncthreads();
        uint32_t aS = sA_u32 + (kc & 1) * 16384;
        uint32_t bS = sB_u32 + (kc & 1) * 8192;
#pragma unroll
        for (int ks = 0; ks < 4; ks++) {
            unsigned a[2][4], b4[2][4];
#pragma unroll
            for (int mt = 0; mt < 2; mt++) {
                int r = wm * 32 + mt * 16 + a_row_off;
                ldsm_x4(a[mt], tile_addr(aS, r, ks * 32 + a_k_off));
            }
#pragma unroll
            for (int p2 = 0; p2 < 2; p2++) {
                int col = wn * 32 + p2 * 16 + b_row_off;
                ldsm_x4(b4[p2], tile_addr(bS, col, ks * 32 + b_k_off));
            }
#pragma unroll
            for (int mt = 0; mt < 2; mt++)
#pragma unroll
                for (int nt = 0; nt < 4; nt++)
                    mma_s8(c[mt][nt], a[mt], &b4[nt >> 1][(nt & 1) * 2]);
        }
        __syncthreads();
    }

    // ---- epilogue: wn0 = gate, wn1 = up (same channel); combine via smem ----
    float xsv[2][2];
#pragma unroll
    for (int mt = 0; mt < 2; mt++) {
#pragma unroll
        for (int hh = 0; hh < 2; hh++) {
            int row = wm * 32 + mt * 16 + g + hh * 8;
            int m = tile * TILE_M + row;
            int tok = g_perm[off + min(m, cnt - 1)];
            xsv[mt][hh] = g_xs[tok];
        }
    }

    if (wn == 0) {
#pragma unroll
        for (int mt = 0; mt < 2; mt++)
#pragma unroll
            for (int nt = 0; nt < 4; nt++)
#pragma unroll
                for (int i = 0; i < 4; i++) {
                    int hh = i >> 1;
                    int row = wm * 32 + mt * 16 + g + hh * 8;
                    int cL = nt * 8 + tig * 2 + (i & 1);
                    float gs = gate_scale[e * IEDIM + p * 32 + cL];
                    epi[row * 36 + cL] = (float)c[mt][nt][i] * xsv[mt][hh] * gs;
                }
    }
    __syncthreads();
    if (wn == 1) {
#pragma unroll
        for (int mt = 0; mt < 2; mt++)
#pragma unroll
            for (int nt = 0; nt < 4; nt++)
#pragma unroll
                for (int i = 0; i < 4; i++) {
                    int hh = i >> 1;
                    int row = wm * 32 + mt * 16 + g + hh * 8;
                    int cL = nt * 8 + tig * 2 + (i & 1);
                    float us = up_scale[e * IEDIM + p * 32 + cL];
                    float u = (float)c[mt][nt][i] * xsv[mt][hh] * us;
                    float gv = epi[row * 36 + cL];
                    float sig = 1.0f / (1.0f + expf(-gv));
                    epi[row * 36 + cL] = gv * sig * u;
                }
    }
    __syncthreads();
#pragma unroll
    for (int q = 0; q < 4; q++) {
        int f4 = t + q * 256;
        int row = f4 >> 3, c4 = f4 & 7;
        int m = tile * TILE_M + row;
        if (m < cnt) {
            int tok = g_perm[off + m];
            *(float4*)(g_inter + (size_t)tok * IEDIM + p * 32 + c4 * 4) =
                *(float4*)(epi + row * 36 + c4 * 4);
        }
    }
}

// ---------------- GEMM2: iq(128) @ down(64 cols) -> out, pipelined ----------------
__global__ __launch_bounds__(256, 2)
void gemm2_kernel(const float* __restrict__ down_scale, float* __restrict__ out) {
    __shared__ __align__(16) char smem[49152];
    char* sA = smem;
    char* sB = smem + 32768;

    int e, tile, cnt, off;
    if (!map_tile(blockIdx.x, e, tile, cnt, off)) return;
    int nb = blockIdx.y;             // 0..15

    int t = threadIdx.x;
    int wid = t >> 5, lane = t & 31;
    int wm = wid & 3, wn = wid >> 2;
    int g = lane >> 2, tig = lane & 3;

    int c[2][4][4];
#pragma unroll
    for (int a = 0; a < 2; a++)
#pragma unroll
        for (int b = 0; b < 4; b++)
#pragma unroll
            for (int i = 0; i < 4; i++) c[a][b][i] = 0;

    int arow = t >> 1;
    int am = tile * TILE_M + arow;
    int atok = g_perm[off + min(am, cnt - 1)];
    const int4* asrc_base = (const int4*)(g_iq + (size_t)atok * IEDIM);
    int achunk0 = (t & 1) * 4;
    int brow = t >> 2;
    int gcol = nb * 64 + brow;
    const int4* bsrc_base = (const int4*)(g_down_t + ((size_t)e * HDIM + gcol) * IEDIM);
    int bchunk0 = (t & 3) * 2;

    uint32_t sA_u32 = smem_u32(sA);
    uint32_t sB_u32 = smem_u32(sB);

    int a_row_off = (lane & 7) + ((lane & 8) ? 8 : 0);
    int a_k_off   = (lane & 16) ? 16 : 0;
    int b_row_off = (lane & 7) + ((lane & 16) ? 8 : 0);
    int b_k_off   = (lane & 8) ? 16 : 0;

    auto load_stage = [&](int kc, int stg) {
        int4* da = (int4*)(sA + stg * 16384 + arow * 128);
        const int4* asrc = asrc_base + kc * 8;
#pragma unroll
        for (int ii = 0; ii < 4; ii++) {
            int ch = achunk0 + ii;
            cp16(&da[ch ^ (arow & 7)], &asrc[ch]);
        }
        int4* db = (int4*)(sB + stg * 8192 + brow * 128);
        const int4* bsrc = bsrc_base + kc * 8;
#pragma unroll
        for (int ii = 0; ii < 2; ii++) {
            int ch = bchunk0 + ii;
            cp16(&db[ch ^ (brow & 7)], &bsrc[ch]);
        }
    };

    load_stage(0, 0);
    cp_commit();

#pragma unroll 1
    for (int kc = 0; kc < IEDIM / 128; kc++) {
        if (kc + 1 < IEDIM / 128) {
            load_stage(kc + 1, (kc + 1) & 1);
            cp_commit();
            cp_wait<1>();
        } else {
            cp_wait<0>();
        }
        __syncthreads();
        uint32_t aS = sA_u32 + (kc & 1) * 16384;
        uint32_t bS = sB_u32 + (kc & 1) * 8192;
#pragma unroll
        for (int ks = 0; ks < 4; ks++) {
            unsigned a[2][4], b4[2][4];
#pragma unroll
            for (int mt = 0; mt < 2; mt++) {
                int r = wm * 32 + mt * 16 + a_row_off;
                ldsm_x4(a[mt], tile_addr(aS, r, ks * 32 + a_k_off));
            }
#pragma unroll
            for (int p2 = 0; p2 < 2; p2++) {
                int col = wn * 32 + p2 * 16 + b_row_off;
                ldsm_x4(b4[p2], tile_addr(bS, col, ks * 32 + b_k_off));
            }
#pragma unroll
            for (int mt = 0; mt < 2; mt++)
#pragma unroll
                for (int nt = 0; nt < 4; nt++)
                    mma_s8(c[mt][nt], a[mt], &b4[nt >> 1][(nt & 1) * 2]);
        }
        __syncthreads();
    }

    // epilogue: direct scaled stores (column index includes wn*32)
#pragma unroll
    for (int mt = 0; mt < 2; mt++) {
#pragma unroll
        for (int hh = 0; hh < 2; hh++) {
            int row = wm * 32 + mt * 16 + g + hh * 8;
            int m = tile * TILE_M + row;
            if (m >= cnt) continue;
            int tok = g_perm[off + m];
            float isv = g_is[tok];
            float* orow = out + (size_t)tok * HDIM + nb * 64;
#pragma unroll
            for (int nt = 0; nt < 4; nt++) {
#pragma unroll
                for (int ii = 0; ii < 2; ii++) {
                    int i = hh * 2 + ii;
                    int cL = wn * 32 + nt * 8 + tig * 2 + ii;
                    float ds = down_scale[e * HDIM + nb * 64 + cL];
                    orow[cL] = (float)c[mt][nt][i] * isv * ds;
                }
            }
        }
    }
}

// ---------------- launch ----------------
extern "C" void kernel_launch(void* const* d_in, const int* in_sizes, int n_in,
                              void* d_out, int out_size) {
    const float* hidden      = (const float*)d_in[0];
    const int*   token_ids   = (const int*)d_in[1];
    const void*  gate_q      = d_in[2];
    const float* gate_scale  = (const float*)d_in[3];
    const void*  up_q        = d_in[4];
    const float* up_scale    = (const float*)d_in[5];
    const void*  down_q      = d_in[6];
    const float* down_scale  = (const float*)d_in[7];
    const int*   t2e         = (const int*)d_in[8];
    float* out = (float*)d_out;

    int T = in_sizes[0] / HDIM;     // 16384

    detect_reset_kernel<<<1, 256>>>(gate_q);

    {
        dim3 grid(HDIM / 32, 512 / 32, NEXP), blk(32, 8);
        pack_w1_kernel<<<grid, blk>>>(gate_q, up_q);
    }
    {
        dim3 grid(HDIM / 32, IEDIM / 32, NEXP), blk(32, 8);
        transpose_down_kernel<<<grid, blk>>>(down_q);
    }

    quant_x_kernel<<<(T + 7) / 8, 256>>>(hidden, token_ids, t2e, T);
    scan_kernel<<<1, 32>>>();
    scatter_kernel<<<(T + 255) / 256, 256>>>(T);

    int ntiles = (T + TILE_M - 1) / TILE_M + NEXP;
    {
        dim3 grid(ntiles, 8);
        gemm1_kernel<<<grid, 256>>>(gate_scale, up_scale);
    }
    quant_i_kernel<<<(T + 7) / 8, 256>>>(T);
    {
        dim3 grid(ntiles, 16);
        gemm2_kernel<<<grid, 256>>>(down_scale, out);
    }
}